// round 3
// baseline (speedup 1.0000x reference)
#include <cuda_runtime.h>
#include <cuda_fp16.h>
#include <stdint.h>

#define D 512               // embedding dim (fixed by problem)
#define EPS 1e-6f
#define NODE_CAP 50000      // capacity of the static fp16 copy

// Runtime index-dtype flag: 1 if edge_index is int64, 0 if int32.
__device__ int g_idx_is64;

// fp16 copy of z: one row = 512 halves = 64 uint4. 51.2 MB.
__device__ uint4 g_zh[(size_t)NODE_CAP * 64];
// exact per-node 1/||z_row|| and sum(z_row), fp32
__device__ float g_inv[NODE_CAP];
__device__ float g_sum[NODE_CAP];

__global__ void detect_idx_dtype_kernel(const int* __restrict__ raw)
{
    __shared__ int any_hi_nonzero;
    if (threadIdx.x == 0) any_hi_nonzero = 0;
    __syncthreads();
    int lo = raw[2 * threadIdx.x];
    int hi = raw[2 * threadIdx.x + 1];
    if (hi != 0 || lo < 0) atomicOr(&any_hi_nonzero, 1);
    __syncthreads();
    if (threadIdx.x == 0) g_idx_is64 = any_hi_nonzero ? 0 : 1;
}

__device__ __forceinline__ uint4 pack8(float4 a, float4 b)
{
    uint4 r;
    __half2 h0 = __floats2half2_rn(a.x, a.y);
    __half2 h1 = __floats2half2_rn(a.z, a.w);
    __half2 h2 = __floats2half2_rn(b.x, b.y);
    __half2 h3 = __floats2half2_rn(b.z, b.w);
    r.x = *reinterpret_cast<unsigned*>(&h0);
    r.y = *reinterpret_cast<unsigned*>(&h1);
    r.z = *reinterpret_cast<unsigned*>(&h2);
    r.w = *reinterpret_cast<unsigned*>(&h3);
    return r;
}

// Pass 1: one warp per node. Stream z row (coalesced float4), compute exact
// fp32 norm and sum, pack fp16 copy (coalesced uint4 stores).
// Layout within a row: uint4 #lane holds float4s {lane, lane+32};
//                      uint4 #lane+32 holds float4s {lane+64, lane+96}.
// Any fixed permutation is fine: dot/norm/sum are permutation-invariant.
__global__ void __launch_bounds__(256)
prep_kernel(const float4* __restrict__ z4, int n_nodes)
{
    int node = (blockIdx.x * blockDim.x + threadIdx.x) >> 5;
    int lane = threadIdx.x & 31;
    if (node >= n_nodes) return;

    const float4* __restrict__ R = z4 + (size_t)node * (D / 4);
    float4 v[4];
#pragma unroll
    for (int j = 0; j < 4; j++) v[j] = R[lane + 32 * j];

    float na2 = 0.f, sa = 0.f;
#pragma unroll
    for (int j = 0; j < 4; j++) {
        float4 a = v[j];
        na2 = fmaf(a.x, a.x, na2);
        na2 = fmaf(a.y, a.y, na2);
        na2 = fmaf(a.z, a.z, na2);
        na2 = fmaf(a.w, a.w, na2);
        sa += a.x + a.y + a.z + a.w;
    }

    uint4* __restrict__ W = g_zh + (size_t)node * 64;
    W[lane]      = pack8(v[0], v[1]);
    W[lane + 32] = pack8(v[2], v[3]);

#pragma unroll
    for (int off = 16; off > 0; off >>= 1) {
        na2 += __shfl_xor_sync(0xFFFFFFFFu, na2, off);
        sa  += __shfl_xor_sync(0xFFFFFFFFu, sa,  off);
    }
    if (lane == 0) {
        g_inv[node] = rsqrtf(na2);
        g_sum[node] = sa;
    }
}

__device__ __forceinline__ float dot8(uint4 a, uint4 b, float acc)
{
    const __half2* ah = reinterpret_cast<const __half2*>(&a);
    const __half2* bh = reinterpret_cast<const __half2*>(&b);
#pragma unroll
    for (int k = 0; k < 4; k++) {
        float2 af = __half22float2(ah[k]);
        float2 bf = __half22float2(bh[k]);
        acc = fmaf(af.x, bf.x, acc);
        acc = fmaf(af.y, bf.y, acc);
    }
    return acc;
}

// Pass 2: one warp per edge. Gather two fp16 rows (1 KB each), dot product
// only; norms/sums come from the precomputed tables.
//   dist^2 = 2 - 2*dot*inva*invb + 2*eps*(sa*inva - sb*invb) + D*eps^2
//   out    = sigmoid(1 - sqrt(max(dist^2, 0)))
__global__ void __launch_bounds__(256)
edge_decoder_h_kernel(const void* __restrict__ edge_index,
                      float* __restrict__ out,
                      int n_edges)
{
    int e = (blockIdx.x * blockDim.x + threadIdx.x) >> 5;
    int lane = threadIdx.x & 31;
    if (e >= n_edges) return;

    long long ia, ib;
    if (g_idx_is64) {
        const long long* ei = (const long long*)edge_index;
        ia = ei[e];
        ib = ei[e + n_edges];
    } else {
        const int* ei = (const int*)edge_index;
        ia = ei[e];
        ib = ei[e + n_edges];
    }

    const uint4* __restrict__ A = g_zh + ia * 64;
    const uint4* __restrict__ B = g_zh + ib * 64;

    uint4 a0 = A[lane], a1 = A[lane + 32];
    uint4 b0 = B[lane], b1 = B[lane + 32];

    float dot = dot8(a0, b0, 0.f);
    dot = dot8(a1, b1, dot);

#pragma unroll
    for (int off = 16; off > 0; off >>= 1)
        dot += __shfl_xor_sync(0xFFFFFFFFu, dot, off);

    if (lane == 0) {
        float inva = g_inv[ia];
        float invb = g_inv[ib];
        float sa   = g_sum[ia];
        float sb   = g_sum[ib];
        float d2 = 2.0f - 2.0f * dot * inva * invb
                 + 2.0f * EPS * (sa * inva - sb * invb)
                 + (float)D * EPS * EPS;
        d2 = fmaxf(d2, 0.0f);
        float v = 1.0f - sqrtf(d2);
        out[e] = 1.0f / (1.0f + __expf(-v));
    }
}

// Fallback (fp32 fused, one warp per edge) if n_nodes exceeds static capacity.
__global__ void __launch_bounds__(256)
edge_decoder_f32_kernel(const float* __restrict__ z,
                        const void* __restrict__ edge_index,
                        float* __restrict__ out,
                        int n_edges)
{
    int e = (blockIdx.x * blockDim.x + threadIdx.x) >> 5;
    int lane = threadIdx.x & 31;
    if (e >= n_edges) return;

    long long ia, ib;
    if (g_idx_is64) {
        const long long* ei = (const long long*)edge_index;
        ia = ei[e];
        ib = ei[e + n_edges];
    } else {
        const int* ei = (const int*)edge_index;
        ia = ei[e];
        ib = ei[e + n_edges];
    }

    const float4* A = reinterpret_cast<const float4*>(z + ia * (long long)D);
    const float4* B = reinterpret_cast<const float4*>(z + ib * (long long)D);

    float dot = 0.f, na2 = 0.f, nb2 = 0.f, sa = 0.f, sb = 0.f;
    float4 av[4], bv[4];
#pragma unroll
    for (int j = 0; j < 4; j++) {
        av[j] = A[lane + 32 * j];
        bv[j] = B[lane + 32 * j];
    }
#pragma unroll
    for (int j = 0; j < 4; j++) {
        float4 a = av[j], b = bv[j];
        dot = fmaf(a.x, b.x, dot); dot = fmaf(a.y, b.y, dot);
        dot = fmaf(a.z, b.z, dot); dot = fmaf(a.w, b.w, dot);
        na2 = fmaf(a.x, a.x, na2); na2 = fmaf(a.y, a.y, na2);
        na2 = fmaf(a.z, a.z, na2); na2 = fmaf(a.w, a.w, na2);
        nb2 = fmaf(b.x, b.x, nb2); nb2 = fmaf(b.y, b.y, nb2);
        nb2 = fmaf(b.z, b.z, nb2); nb2 = fmaf(b.w, b.w, nb2);
        sa += a.x + a.y + a.z + a.w;
        sb += b.x + b.y + b.z + b.w;
    }
#pragma unroll
    for (int off = 16; off > 0; off >>= 1) {
        dot += __shfl_xor_sync(0xFFFFFFFFu, dot, off);
        na2 += __shfl_xor_sync(0xFFFFFFFFu, na2, off);
        nb2 += __shfl_xor_sync(0xFFFFFFFFu, nb2, off);
        sa  += __shfl_xor_sync(0xFFFFFFFFu, sa,  off);
        sb  += __shfl_xor_sync(0xFFFFFFFFu, sb,  off);
    }
    if (lane == 0) {
        float inva = rsqrtf(na2);
        float invb = rsqrtf(nb2);
        float d2 = 2.0f - 2.0f * dot * inva * invb
                 + 2.0f * EPS * (sa * inva - sb * invb)
                 + (float)D * EPS * EPS;
        d2 = fmaxf(d2, 0.0f);
        float v = 1.0f - sqrtf(d2);
        out[e] = 1.0f / (1.0f + __expf(-v));
    }
}

extern "C" void kernel_launch(void* const* d_in, const int* in_sizes, int n_in,
                              void* d_out, int out_size)
{
    const float* z = (const float*)d_in[0];
    const void* edge_index = d_in[1];
    float* out = (float*)d_out;

    int n_nodes = in_sizes[0] / D;
    int n_edges = in_sizes[1] / 2;

    detect_idx_dtype_kernel<<<1, 512>>>((const int*)edge_index);

    int warps_per_block = 256 / 32;
    int egrid = (n_edges + warps_per_block - 1) / warps_per_block;

    if (n_nodes <= NODE_CAP) {
        int ngrid = (n_nodes + warps_per_block - 1) / warps_per_block;
        prep_kernel<<<ngrid, 256>>>((const float4*)z, n_nodes);
        edge_decoder_h_kernel<<<egrid, 256>>>(edge_index, out, n_edges);
    } else {
        edge_decoder_f32_kernel<<<egrid, 256>>>(z, edge_index, out, n_edges);
    }
}